// round 1
// baseline (speedup 1.0000x reference)
#include <cuda_runtime.h>
#include <math.h>

// Problem constants (validated against in_sizes at launch)
#define NN 50000
#define EE 850000

// -------- device scratch (no allocations allowed) --------
__device__ int g_deg[NN];
__device__ int g_cursor[NN];
__device__ int g_rowptr[NN + 1];
__device__ int g_srcs[EE];
__device__ float g_xl[(size_t)NN * 128];
__device__ float g_xr[(size_t)NN * 128];
__device__ float g_h[(size_t)NN * 128];

// ---------------- CSR build ----------------

__global__ void zero_deg_kernel(int n) {
    int i = blockIdx.x * blockDim.x + threadIdx.x;
    if (i < n) g_deg[i] = 0;
}

__global__ void count_kernel(const int* __restrict__ dst, int e) {
    int i = blockIdx.x * blockDim.x + threadIdx.x;
    if (i < e) atomicAdd(&g_deg[dst[i]], 1);
}

// single-block exclusive scan over 50k degrees (1024 threads x 49-elem chunks)
__global__ void scan_kernel(int n) {
    __shared__ int sdata[1024];
    int t = threadIdx.x;
    int ch = (n + 1023) >> 10;
    int s0 = t * ch;
    int s1 = min(s0 + ch, n);
    int sum = 0;
    for (int i = s0; i < s1; i++) sum += g_deg[i];
    sdata[t] = sum;
    __syncthreads();
    // Hillis-Steele inclusive scan
    for (int off = 1; off < 1024; off <<= 1) {
        int v = (t >= off) ? sdata[t - off] : 0;
        __syncthreads();
        sdata[t] += v;
        __syncthreads();
    }
    int run = sdata[t] - sum;  // exclusive prefix for this chunk
    for (int i = s0; i < s1; i++) {
        g_rowptr[i] = run;
        g_cursor[i] = run;
        run += g_deg[i];
    }
    if (t == 1023) g_rowptr[n] = run;  // == E
}

__global__ void scatter_kernel(const int* __restrict__ src,
                               const int* __restrict__ dst, int e) {
    int i = blockIdx.x * blockDim.x + threadIdx.x;
    if (i < e) {
        int d = dst[i];
        int p = atomicAdd(&g_cursor[d], 1);
        g_srcs[p] = src[i];
    }
}

// ---------------- linear: y = x @ W^T + b ----------------
// W: [fout, fin] row-major. Transposed into smem as sW[k*fout + o].
// Each thread computes 4 consecutive outputs (LDS.128 on weights).
__global__ void linear_kernel(const float* __restrict__ x,
                              const float* __restrict__ W,
                              const float* __restrict__ b,
                              float* __restrict__ y,
                              int n, int fin, int fout) {
    __shared__ float sW[8192];   // fin*fout == 8192 for both layers
    __shared__ float sX[2048];   // up to P*fin floats

    int tid = threadIdx.x;  // 256 threads
    int wn = fin * fout;
    for (int idx = tid; idx < wn; idx += 256) {
        int o = idx / fin;
        int k = idx - o * fin;
        sW[k * fout + o] = W[idx];
    }

    int TPN = fout >> 2;        // threads per node (32 or 16)
    int P = 256 / TPN;          // nodes per iteration (8 or 16)
    int sub = tid / TPN;
    int ot = tid - sub * TPN;   // output quad index
    float4 bv = *(const float4*)(b + 4 * ot);

    int groups = (n + P - 1) / P;
    for (int g = blockIdx.x; g < groups; g += gridDim.x) {
        int base = g * P;
        __syncthreads();  // protects sX reuse (and first-iter sW load)
        int xcount = P * fin;
        for (int idx = tid; idx < xcount; idx += 256) {
            int nn = base + idx / fin;
            sX[idx] = (nn < n) ? x[(size_t)nn * fin + (idx % fin)] : 0.f;
        }
        __syncthreads();

        int node = base + sub;
        if (node < n) {
            float4 acc = bv;
            const float4* xs4 = (const float4*)(sX + sub * fin);
            int kq = fin >> 2;
            for (int k4 = 0; k4 < kq; k4++) {
                float4 xv = xs4[k4];
                const float* wbase = sW + (k4 * 4) * fout + 4 * ot;
                float4 w0 = *(const float4*)(wbase);
                float4 w1 = *(const float4*)(wbase + fout);
                float4 w2 = *(const float4*)(wbase + 2 * fout);
                float4 w3 = *(const float4*)(wbase + 3 * fout);
                acc.x += xv.x * w0.x + xv.y * w1.x + xv.z * w2.x + xv.w * w3.x;
                acc.y += xv.x * w0.y + xv.y * w1.y + xv.z * w2.y + xv.w * w3.y;
                acc.z += xv.x * w0.z + xv.y * w1.z + xv.z * w2.z + xv.w * w3.z;
                acc.w += xv.x * w0.w + xv.y * w1.w + xv.z * w2.w + xv.w * w3.w;
            }
            *(float4*)(y + (size_t)node * fout + 4 * ot) = acc;
        }
    }
}

// ---------------- fused GATv2 edge phase ----------------
// One warp per destination node; online softmax fused with aggregation so
// xl[src] is gathered exactly once per edge.
template <int H, int C, bool ELU>
__global__ void gat_kernel(const float* __restrict__ xl,
                           const float* __restrict__ xr,
                           const float* __restrict__ att,
                           const float* __restrict__ bias,
                           float* __restrict__ out, int n) {
    constexpr int F = H * C;      // 128 or 64
    constexpr int V = F / 32;     // floats per lane (4 or 2)
    constexpr int G = 32 / H;     // lanes per head group (8 or 32)

    int wid = (blockIdx.x * blockDim.x + threadIdx.x) >> 5;
    int lane = threadIdx.x & 31;
    if (wid >= n) return;
    int i = wid;
    int cbase = lane * V;

    float xrv[V], attv[V], acc[V];
    {
        const float* xp = xr + (size_t)i * F + cbase;
        if constexpr (V == 4) {
            float4 t = *(const float4*)xp;
            xrv[0] = t.x; xrv[1] = t.y; xrv[2] = t.z; xrv[3] = t.w;
        } else {
            float2 t = *(const float2*)xp;
            xrv[0] = t.x; xrv[1] = t.y;
        }
    }
#pragma unroll
    for (int j = 0; j < V; j++) { attv[j] = att[cbase + j]; acc[j] = 0.f; }

    float m = -1e30f, z = 0.f;
    int beg = g_rowptr[i], end = g_rowptr[i + 1];

    for (int k = beg; k < end; k++) {
        int src = g_srcs[k];
        float xlv[V];
        const float* lp = xl + (size_t)src * F + cbase;
        if constexpr (V == 4) {
            float4 t = *(const float4*)lp;
            xlv[0] = t.x; xlv[1] = t.y; xlv[2] = t.z; xlv[3] = t.w;
        } else {
            float2 t = *(const float2*)lp;
            xlv[0] = t.x; xlv[1] = t.y;
        }
        float part = 0.f;
#pragma unroll
        for (int j = 0; j < V; j++) {
            float s = xlv[j] + xrv[j];
            s = (s > 0.f) ? s : 0.2f * s;   // LeakyReLU(0.2)
            part += s * attv[j];
        }
        // reduce within head group (aligned power-of-2 lane groups)
#pragma unroll
        for (int off = G / 2; off > 0; off >>= 1)
            part += __shfl_xor_sync(0xffffffffu, part, off);
        float e = part;

        float nm = fmaxf(m, e);
        float sc = __expf(m - nm);
        float p = __expf(e - nm);
        z = z * sc + p;
#pragma unroll
        for (int j = 0; j < V; j++) acc[j] = acc[j] * sc + p * xlv[j];
        m = nm;
    }

    float inv = 1.f / (z + 1e-16f);
    float ov[V];
#pragma unroll
    for (int j = 0; j < V; j++) {
        float v = acc[j] * inv + bias[cbase + j];
        if constexpr (ELU) v = (v > 0.f) ? v : (__expf(v) - 1.f);
        ov[j] = v;
    }
    float* op = out + (size_t)i * F + cbase;
    if constexpr (V == 4)
        *(float4*)op = make_float4(ov[0], ov[1], ov[2], ov[3]);
    else
        *(float2*)op = make_float2(ov[0], ov[1]);
}

// ---------------- launch ----------------

extern "C" void kernel_launch(void* const* d_in, const int* in_sizes, int n_in,
                              void* d_out, int out_size) {
    const float* x    = (const float*)d_in[0];
    const int*   ei   = (const int*)d_in[1];
    const float* Wl1  = (const float*)d_in[2];
    const float* bl1  = (const float*)d_in[3];
    const float* Wr1  = (const float*)d_in[4];
    const float* br1  = (const float*)d_in[5];
    const float* att1 = (const float*)d_in[6];
    const float* bias1= (const float*)d_in[7];
    const float* Wl2  = (const float*)d_in[8];
    const float* bl2  = (const float*)d_in[9];
    const float* Wr2  = (const float*)d_in[10];
    const float* br2  = (const float*)d_in[11];
    const float* att2 = (const float*)d_in[12];
    const float* bias2= (const float*)d_in[13];
    float* out = (float*)d_out;

    int n = in_sizes[0] / 64;   // 50000
    int e = in_sizes[1] / 2;    // 850000
    const int* src = ei;
    const int* dst = ei + e;

    float *xlp, *xrp, *hp;
    cudaGetSymbolAddress((void**)&xlp, g_xl);
    cudaGetSymbolAddress((void**)&xrp, g_xr);
    cudaGetSymbolAddress((void**)&hp,  g_h);

    // CSR by dst
    zero_deg_kernel<<<(n + 255) / 256, 256>>>(n);
    count_kernel<<<(e + 255) / 256, 256>>>(dst, e);
    scan_kernel<<<1, 1024>>>(n);
    scatter_kernel<<<(e + 255) / 256, 256>>>(src, dst, e);

    // layer 1: 64 -> 4x32 (concat) -> ELU
    linear_kernel<<<1184, 256>>>(x, Wl1, bl1, xlp, n, 64, 128);
    linear_kernel<<<1184, 256>>>(x, Wr1, br1, xrp, n, 64, 128);
    gat_kernel<4, 32, true><<<(n + 7) / 8, 256>>>(xlp, xrp, att1, bias1, hp, n);

    // layer 2: 128 -> 1x64 (mean over 1 head == identity)
    linear_kernel<<<1184, 256>>>(hp, Wl2, bl2, xlp, n, 128, 64);
    linear_kernel<<<1184, 256>>>(hp, Wr2, br2, xrp, n, 128, 64);
    gat_kernel<1, 64, false><<<(n + 7) / 8, 256>>>(xlp, xrp, att2, bias2, out, n);
}

// round 2
// speedup vs baseline: 1.8355x; 1.8355x over previous
#include <cuda_runtime.h>
#include <math.h>

#define NN 50000
#define EE 850000

// -------- device scratch (no allocations allowed) --------
__device__ int g_deg[NN];
__device__ int g_cursor[NN];
__device__ int g_rowptr[NN + 1];
__device__ int g_srcs[EE];
__device__ float g_xl[(size_t)NN * 128];
__device__ float g_xr[(size_t)NN * 128];
__device__ float g_h[(size_t)NN * 128];

// ---------------- CSR build ----------------

__global__ void count_kernel(const int* __restrict__ dst, int e) {
    int i = blockIdx.x * blockDim.x + threadIdx.x;
    if (i < e) atomicAdd(&g_deg[dst[i]], 1);
}

// single-block exclusive scan over 50k degrees
__global__ void scan_kernel(int n) {
    __shared__ int sdata[1024];
    int t = threadIdx.x;
    int ch = (n + 1023) >> 10;
    int s0 = t * ch;
    int s1 = min(s0 + ch, n);
    int sum = 0;
    for (int i = s0; i < s1; i++) sum += g_deg[i];
    sdata[t] = sum;
    __syncthreads();
    for (int off = 1; off < 1024; off <<= 1) {
        int v = (t >= off) ? sdata[t - off] : 0;
        __syncthreads();
        sdata[t] += v;
        __syncthreads();
    }
    int run = sdata[t] - sum;
    for (int i = s0; i < s1; i++) {
        g_rowptr[i] = run;
        g_cursor[i] = run;
        run += g_deg[i];
    }
    if (t == 1023) g_rowptr[n] = run;
}

__global__ void scatter_kernel(const int* __restrict__ src,
                               const int* __restrict__ dst, int e) {
    int i = blockIdx.x * blockDim.x + threadIdx.x;
    if (i < e) {
        int d = dst[i];
        int p = atomicAdd(&g_cursor[d], 1);
        g_srcs[p] = src[i];
    }
}

// ---------------- register-tiled dual linear: y = x @ W^T + b ----------------
// blockIdx.y selects (W0,b0,y0) vs (W1,b1,y1) — both GEMMs share the same x.
// Block covers 64 nodes; thread tile NPT nodes x 4 outs; k-chunks of 32 staged
// transposed in smem (sX[k][node], sW[k][out]) so the inner loop is
// 3x LDS.128 per 32 FFMA (FFMA-bound).
template <int FIN, int FOUT>
__global__ void linear2_kernel(const float* __restrict__ x,
                               const float* __restrict__ W0,
                               const float* __restrict__ b0,
                               float* __restrict__ y0,
                               const float* __restrict__ W1,
                               const float* __restrict__ b1,
                               float* __restrict__ y1,
                               int n) {
    constexpr int BN = 64;           // nodes per block
    constexpr int KC = 32;           // k chunk
    constexpr int OT = FOUT / 4;     // out-dim threads (32 or 16)
    constexpr int NT = 256 / OT;     // node-dim threads (8 or 16)
    constexpr int NPT = BN / NT;     // nodes per thread (8 or 4)

    __shared__ float sW[KC * FOUT];  // <=16KB
    __shared__ float sX[KC * BN];    //   8KB

    const float* W = blockIdx.y ? W1 : W0;
    const float* b = blockIdx.y ? b1 : b0;
    float* y = blockIdx.y ? y1 : y0;

    int tid = threadIdx.x;
    int ot = tid % OT;
    int nt = tid / OT;
    int nbase = blockIdx.x * BN;
    int n0 = nt * NPT;

    float acc[NPT][4];
#pragma unroll
    for (int i = 0; i < NPT; i++)
#pragma unroll
        for (int j = 0; j < 4; j++) acc[i][j] = 0.f;

    for (int kc = 0; kc < FIN; kc += KC) {
        __syncthreads();
        // stage W chunk transposed: sW[k][o] = W[o][kc+k]
        for (int idx = tid; idx < (KC / 4) * FOUT; idx += 256) {
            int o = idx >> 3;           // KC/4 == 8 float4 per out row
            int kq = (idx & 7) * 4;
            float4 w = *(const float4*)(W + (size_t)o * FIN + kc + kq);
            sW[(kq + 0) * FOUT + o] = w.x;
            sW[(kq + 1) * FOUT + o] = w.y;
            sW[(kq + 2) * FOUT + o] = w.z;
            sW[(kq + 3) * FOUT + o] = w.w;
        }
        // stage X chunk transposed: sX[k][nn] = x[nbase+nn][kc+k]
        for (int idx = tid; idx < (KC / 4) * BN; idx += 256) {
            int nn = idx >> 3;
            int kq = (idx & 7) * 4;
            int node = nbase + nn;
            float4 xv = make_float4(0.f, 0.f, 0.f, 0.f);
            if (node < n) xv = *(const float4*)(x + (size_t)node * FIN + kc + kq);
            sX[(kq + 0) * BN + nn] = xv.x;
            sX[(kq + 1) * BN + nn] = xv.y;
            sX[(kq + 2) * BN + nn] = xv.z;
            sX[(kq + 3) * BN + nn] = xv.w;
        }
        __syncthreads();

#pragma unroll
        for (int k = 0; k < KC; k++) {
            float4 wv = *(const float4*)(sW + k * FOUT + 4 * ot);
#pragma unroll
            for (int q = 0; q < NPT / 4; q++) {
                float4 xv = *(const float4*)(sX + k * BN + n0 + 4 * q);
                float xs[4] = {xv.x, xv.y, xv.z, xv.w};
#pragma unroll
                for (int r = 0; r < 4; r++) {
                    acc[4 * q + r][0] += xs[r] * wv.x;
                    acc[4 * q + r][1] += xs[r] * wv.y;
                    acc[4 * q + r][2] += xs[r] * wv.z;
                    acc[4 * q + r][3] += xs[r] * wv.w;
                }
            }
        }
    }

    float4 bv = *(const float4*)(b + 4 * ot);
#pragma unroll
    for (int i = 0; i < NPT; i++) {
        int node = nbase + n0 + i;
        if (node < n) {
            float4 o4 = make_float4(acc[i][0] + bv.x, acc[i][1] + bv.y,
                                    acc[i][2] + bv.z, acc[i][3] + bv.w);
            *(float4*)(y + (size_t)node * FOUT + 4 * ot) = o4;
        }
    }
}

// ---------------- fused GATv2 edge phase ----------------
// One warp per destination node; online softmax fused with aggregation.
// 2-way software pipeline: both gathers of a pair issue before the dependent
// shfl/exp chain.
template <int H, int C, bool ELU>
__global__ void gat_kernel(const float* __restrict__ xl,
                           const float* __restrict__ xr,
                           const float* __restrict__ att,
                           const float* __restrict__ bias,
                           float* __restrict__ out, int n) {
    constexpr int F = H * C;
    constexpr int V = F / 32;
    constexpr int G = 32 / H;

    int wid = (blockIdx.x * blockDim.x + threadIdx.x) >> 5;
    int lane = threadIdx.x & 31;
    if (wid >= n) return;
    int i = wid;
    int cbase = lane * V;

    float xrv[V], attv[V], acc[V];
    {
        const float* xp = xr + (size_t)i * F + cbase;
        if constexpr (V == 4) {
            float4 t = *(const float4*)xp;
            xrv[0] = t.x; xrv[1] = t.y; xrv[2] = t.z; xrv[3] = t.w;
        } else {
            float2 t = *(const float2*)xp;
            xrv[0] = t.x; xrv[1] = t.y;
        }
    }
#pragma unroll
    for (int j = 0; j < V; j++) { attv[j] = att[cbase + j]; acc[j] = 0.f; }

    float m = -1e30f, z = 0.f;
    int beg = g_rowptr[i], end = g_rowptr[i + 1];

    auto process = [&](const float* __restrict__ xlv) {
        float part = 0.f;
#pragma unroll
        for (int j = 0; j < V; j++) {
            float s = xlv[j] + xrv[j];
            s = (s > 0.f) ? s : 0.2f * s;
            part += s * attv[j];
        }
#pragma unroll
        for (int off = G / 2; off > 0; off >>= 1)
            part += __shfl_xor_sync(0xffffffffu, part, off);
        float e = part;
        float nm = fmaxf(m, e);
        float sc = __expf(m - nm);
        float p = __expf(e - nm);
        z = z * sc + p;
#pragma unroll
        for (int j = 0; j < V; j++) acc[j] = acc[j] * sc + p * xlv[j];
        m = nm;
    };

    int k = beg;
    for (; k + 1 < end; k += 2) {
        int s0 = g_srcs[k];
        int s1 = g_srcs[k + 1];
        float a0[V], a1[V];
        const float* p0 = xl + (size_t)s0 * F + cbase;
        const float* p1 = xl + (size_t)s1 * F + cbase;
        if constexpr (V == 4) {
            float4 t0 = *(const float4*)p0;
            float4 t1 = *(const float4*)p1;
            a0[0] = t0.x; a0[1] = t0.y; a0[2] = t0.z; a0[3] = t0.w;
            a1[0] = t1.x; a1[1] = t1.y; a1[2] = t1.z; a1[3] = t1.w;
        } else {
            float2 t0 = *(const float2*)p0;
            float2 t1 = *(const float2*)p1;
            a0[0] = t0.x; a0[1] = t0.y;
            a1[0] = t1.x; a1[1] = t1.y;
        }
        process(a0);
        process(a1);
    }
    if (k < end) {
        int s0 = g_srcs[k];
        float a0[V];
        const float* p0 = xl + (size_t)s0 * F + cbase;
        if constexpr (V == 4) {
            float4 t0 = *(const float4*)p0;
            a0[0] = t0.x; a0[1] = t0.y; a0[2] = t0.z; a0[3] = t0.w;
        } else {
            float2 t0 = *(const float2*)p0;
            a0[0] = t0.x; a0[1] = t0.y;
        }
        process(a0);
    }

    float inv = 1.f / (z + 1e-16f);
    float ov[V];
#pragma unroll
    for (int j = 0; j < V; j++) {
        float v = acc[j] * inv + bias[cbase + j];
        if constexpr (ELU) v = (v > 0.f) ? v : (__expf(v) - 1.f);
        ov[j] = v;
    }
    float* op = out + (size_t)i * F + cbase;
    if constexpr (V == 4)
        *(float4*)op = make_float4(ov[0], ov[1], ov[2], ov[3]);
    else
        *(float2*)op = make_float2(ov[0], ov[1]);
}

// ---------------- launch ----------------

extern "C" void kernel_launch(void* const* d_in, const int* in_sizes, int n_in,
                              void* d_out, int out_size) {
    const float* x    = (const float*)d_in[0];
    const int*   ei   = (const int*)d_in[1];
    const float* Wl1  = (const float*)d_in[2];
    const float* bl1  = (const float*)d_in[3];
    const float* Wr1  = (const float*)d_in[4];
    const float* br1  = (const float*)d_in[5];
    const float* att1 = (const float*)d_in[6];
    const float* bias1= (const float*)d_in[7];
    const float* Wl2  = (const float*)d_in[8];
    const float* bl2  = (const float*)d_in[9];
    const float* Wr2  = (const float*)d_in[10];
    const float* br2  = (const float*)d_in[11];
    const float* att2 = (const float*)d_in[12];
    const float* bias2= (const float*)d_in[13];
    float* out = (float*)d_out;

    int n = in_sizes[0] / 64;   // 50000
    int e = in_sizes[1] / 2;    // 850000
    const int* src = ei;
    const int* dst = ei + e;

    float *xlp, *xrp, *hp;
    int* degp;
    cudaGetSymbolAddress((void**)&xlp, g_xl);
    cudaGetSymbolAddress((void**)&xrp, g_xr);
    cudaGetSymbolAddress((void**)&hp,  g_h);
    cudaGetSymbolAddress((void**)&degp, g_deg);

    // CSR by dst
    cudaMemsetAsync(degp, 0, n * sizeof(int));
    count_kernel<<<(e + 255) / 256, 256>>>(dst, e);
    scan_kernel<<<1, 1024>>>(n);
    scatter_kernel<<<(e + 255) / 256, 256>>>(src, dst, e);

    dim3 lgrid((n + 63) / 64, 2);

    // layer 1: 64 -> 4x32 (concat) -> ELU
    linear2_kernel<64, 128><<<lgrid, 256>>>(x, Wl1, bl1, xlp, Wr1, br1, xrp, n);
    gat_kernel<4, 32, true><<<(n + 7) / 8, 256>>>(xlp, xrp, att1, bias1, hp, n);

    // layer 2: 128 -> 1x64 (mean over 1 head == identity)
    linear2_kernel<128, 64><<<lgrid, 256>>>(hp, Wl2, bl2, xlp, Wr2, br2, xrp, n);
    gat_kernel<1, 64, false><<<(n + 7) / 8, 256>>>(xlp, xrp, att2, bias2, out, n);
}